// round 5
// baseline (speedup 1.0000x reference)
#include <cuda_runtime.h>

// VQC_Registers_BS_density — analytic collapse (see prior rounds):
// 16-layer circuit = R_a(sum theta_even) (x) R_b(sum theta_odd);
// rho' = U rho U^T = four independent pairwise Givens mixes on the tensor
// indices (a1, b1, a2, b2) of rho[32,32,32,32]. 8 MB total traffic.
//
// Round 5: shuffle-free. Each thread owns rows {r0, r0+1, r0+32, r0+33} x
// cols {c..c+3, c+32..c+35} (32 floats, 8x LDG.128 / 8x STG.128), so all four
// mixes are thread-local register ops. 32768 threads, single wave
// (128 blocks x 256 threads, 1 CTA/SM). Loads issued first; angle sum +
// MUFU sincos overlap their latency.

__device__ __forceinline__ void rot(float& a, float& b, float c, float s)
{
    float t = c * a - s * b;
    b = s * a + c * b;
    a = t;
}

__global__ __launch_bounds__(256) void vqc_bs_density_kernel(
    const float* __restrict__ rho,
    const float* __restrict__ angles,
    float* __restrict__ out)
{
    const int tid = blockIdx.x * 256 + threadIdx.x;  // 0..32767

    // tid bits: u=[0:3) (float4 within 32-col half), p=[3:7) (64-col block),
    //           m=[7:11) (b1 pair), k=[11:15) (a1 pair)
    const int u = tid & 7;
    const int p = (tid >> 3) & 15;
    const int m = (tid >> 7) & 15;
    const int k = tid >> 11;

    const int c  = (p << 6) + (u << 2);    // 64p + 4u   (partner cols at c+32)
    const int r0 = (k << 6) + (m << 1);    // 32*(2k) + 2m

    const float* base  = rho + r0 * 1024 + c;
    float*       obase = out + r0 * 1024 + c;

    // x[row][col]: rows {r0, r0+1, r0+32, r0+33}, cols {c..c+3, c+32..c+35}
    const int roff[4] = { 0, 1024, 32768, 33792 };
    float x[4][8];

    // Issue all 8 loads first; angle math below overlaps their latency.
#pragma unroll
    for (int r = 0; r < 4; r++) {
        const float4 lo = *reinterpret_cast<const float4*>(base + roff[r]);
        const float4 hi = *reinterpret_cast<const float4*>(base + roff[r] + 32);
        x[r][0] = lo.x; x[r][1] = lo.y; x[r][2] = lo.z; x[r][3] = lo.w;
        x[r][4] = hi.x; x[r][5] = hi.y; x[r][6] = hi.z; x[r][7] = hi.w;
    }

    // Composed angles (uniform; 4x LDG.128 broadcast, tree-sum, MUFU sincos).
    const float4* a4 = reinterpret_cast<const float4*>(angles);
    const float4 A0 = __ldg(a4 + 0), A1 = __ldg(a4 + 1);
    const float4 A2 = __ldg(a4 + 2), A3 = __ldg(a4 + 3);
    const float suma = (A0.x + A0.z) + (A1.x + A1.z)
                     + (A2.x + A2.z) + (A3.x + A3.z);
    const float sumb = (A0.y + A0.w) + (A1.y + A1.w)
                     + (A2.y + A2.w) + (A3.y + A3.w);
    float ca, sa, cb, sb;
    __sincosf(suma, &sa, &ca);
    __sincosf(sumb, &sb, &cb);

    // a1 mix (ca,sa): rows 0<->2, 1<->3 (r0 <-> r0+32)
#pragma unroll
    for (int j = 0; j < 8; j++) {
        rot(x[0][j], x[2][j], ca, sa);
        rot(x[1][j], x[3][j], ca, sa);
    }
    // b1 mix (cb,sb): rows 0<->1, 2<->3 (r0 <-> r0+1)
#pragma unroll
    for (int j = 0; j < 8; j++) {
        rot(x[0][j], x[1][j], cb, sb);
        rot(x[2][j], x[3][j], cb, sb);
    }
    // a2 mix (ca,sa): cols j <-> j+4 (c+i <-> c+32+i)
#pragma unroll
    for (int r = 0; r < 4; r++) {
        rot(x[r][0], x[r][4], ca, sa);
        rot(x[r][1], x[r][5], ca, sa);
        rot(x[r][2], x[r][6], ca, sa);
        rot(x[r][3], x[r][7], ca, sa);
    }
    // b2 mix (cb,sb): col pairs (0,1),(2,3),(4,5),(6,7)
#pragma unroll
    for (int r = 0; r < 4; r++) {
        rot(x[r][0], x[r][1], cb, sb);
        rot(x[r][2], x[r][3], cb, sb);
        rot(x[r][4], x[r][5], cb, sb);
        rot(x[r][6], x[r][7], cb, sb);
    }

#pragma unroll
    for (int r = 0; r < 4; r++) {
        float4 lo, hi;
        lo.x = x[r][0]; lo.y = x[r][1]; lo.z = x[r][2]; lo.w = x[r][3];
        hi.x = x[r][4]; hi.y = x[r][5]; hi.z = x[r][6]; hi.w = x[r][7];
        *reinterpret_cast<float4*>(obase + roff[r])      = lo;
        *reinterpret_cast<float4*>(obase + roff[r] + 32) = hi;
    }
}

extern "C" void kernel_launch(void* const* d_in, const int* in_sizes, int n_in,
                              void* d_out, int out_size)
{
    const float* rho    = (const float*)d_in[0];  // input_state [1024,1024] f32
    const float* angles = (const float*)d_in[1];  // [16] f32
    // d_in[2..4]: cos/sin/id stacks — analytically folded away, never read.
    float* out = (float*)d_out;

    // 32768 threads, single wave: 128 blocks x 256 threads (1 CTA/SM).
    vqc_bs_density_kernel<<<128, 256>>>(rho, angles, out);
}

// round 6
// speedup vs baseline: 1.0338x; 1.0338x over previous
#include <cuda_runtime.h>

// VQC_Registers_BS_density — analytic collapse (see prior rounds):
// 16-layer circuit = R_a(sum theta_even) (x) R_b(sum theta_odd);
// rho' = U rho U^T = four independent pairwise Givens mixes on the tensor
// indices (a1, b1, a2, b2) of rho[32,32,32,32]. 8 MB total traffic; the 48 MB
// of gate matrices are never read.
//
// Round 6 = Round-4 structure (65536 threads, 4x LDG.128 + 4x STG.128,
// a2 mix via shfl_xor(8)) with the critical-path tail shortened:
//  * angle loads issued BEFORE the data loads (sincos chain overlaps them)
//  * a2 shuffle mix applied per-row as each load lands (shuffle latency
//    overlaps the remaining in-flight loads); tail is pure FMA -> STG.

__device__ __forceinline__ void rot(float& a, float& b, float c, float s)
{
    float t = c * a - s * b;
    b = s * a + c * b;
    a = t;
}

// a2 Givens mix across lane^8: e' = ca*e + sg*partner (sg = +/-sa by v-half).
__device__ __forceinline__ void mix8(float4& y, float ca, float sg)
{
    float p;
    p = __shfl_xor_sync(0xffffffffu, y.x, 8);  y.x = ca * y.x + sg * p;
    p = __shfl_xor_sync(0xffffffffu, y.y, 8);  y.y = ca * y.y + sg * p;
    p = __shfl_xor_sync(0xffffffffu, y.z, 8);  y.z = ca * y.z + sg * p;
    p = __shfl_xor_sync(0xffffffffu, y.w, 8);  y.w = ca * y.w + sg * p;
}

__global__ __launch_bounds__(512) void vqc_bs_density_kernel(
    const float* __restrict__ rho,
    const float* __restrict__ angles,
    float* __restrict__ out)
{
    const int tid = blockIdx.x * 512 + threadIdx.x;  // 0..65535

    // Composed angles first (uniform; 4x LDG.128 broadcast). Their latency and
    // the sum/sincos chain overlap the data loads issued just below.
    const float4* a4 = reinterpret_cast<const float4*>(angles);
    const float4 A0 = __ldg(a4 + 0), A1 = __ldg(a4 + 1);
    const float4 A2 = __ldg(a4 + 2), A3 = __ldg(a4 + 3);

    // lane bits: [0:3)=u (float4 within 32-col half), [3]=v (a2 half).
    const int lane = tid & 31;
    const int P    = (tid >> 5) & 7;
    const int m    = (tid >> 8) & 15;
    const int k    = tid >> 12;

    const int c  = ((lane & 7) << 2) + ((lane >> 3) << 5) + (P << 7);
    const int v  = (lane >> 3) & 1;
    const int r0 = (k << 6) + (m << 1);    // 32*(2k) + 2m

    const float* base  = rho + r0 * 1024 + c;
    float*       obase = out + r0 * 1024 + c;

    // Rows: y00=r0 (i1=0,j1=0), y01=r0+1 (j1=1), y10=r0+32 (i1=1), y11=r0+33.
    float4 y00 = *reinterpret_cast<const float4*>(base);
    float4 y01 = *reinterpret_cast<const float4*>(base + 1024);
    float4 y10 = *reinterpret_cast<const float4*>(base + 32768);
    float4 y11 = *reinterpret_cast<const float4*>(base + 33792);

    // Angle math (overlaps the loads above).
    const float suma = (A0.x + A0.z) + (A1.x + A1.z)
                     + (A2.x + A2.z) + (A3.x + A3.z);
    const float sumb = (A0.y + A0.w) + (A1.y + A1.w)
                     + (A2.y + A2.w) + (A3.y + A3.w);
    float ca, sa, cb, sb;
    __sincosf(suma, &sa, &ca);
    __sincosf(sumb, &sb, &cb);
    const float sg = v ? sa : -sa;

    // a2 mix FIRST, per row as each load lands: shuffle latency overlaps the
    // remaining in-flight loads instead of sitting on the tail.
    mix8(y00, ca, sg);
    mix8(y01, ca, sg);
    mix8(y10, ca, sg);
    mix8(y11, ca, sg);

    // a1 mix (ca,sa): rows r0 <-> r0+32
    rot(y00.x, y10.x, ca, sa);  rot(y00.y, y10.y, ca, sa);
    rot(y00.z, y10.z, ca, sa);  rot(y00.w, y10.w, ca, sa);
    rot(y01.x, y11.x, ca, sa);  rot(y01.y, y11.y, ca, sa);
    rot(y01.z, y11.z, ca, sa);  rot(y01.w, y11.w, ca, sa);

    // b1 mix (cb,sb): rows r0 <-> r0+1
    rot(y00.x, y01.x, cb, sb);  rot(y00.y, y01.y, cb, sb);
    rot(y00.z, y01.z, cb, sb);  rot(y00.w, y01.w, cb, sb);
    rot(y10.x, y11.x, cb, sb);  rot(y10.y, y11.y, cb, sb);
    rot(y10.z, y11.z, cb, sb);  rot(y10.w, y11.w, cb, sb);

    // b2 mix (cb,sb): within float4, col pairs (c,c+1) and (c+2,c+3).
    // Store each row as soon as it is final to start draining early.
    rot(y00.x, y00.y, cb, sb);  rot(y00.z, y00.w, cb, sb);
    *reinterpret_cast<float4*>(obase) = y00;
    rot(y01.x, y01.y, cb, sb);  rot(y01.z, y01.w, cb, sb);
    *reinterpret_cast<float4*>(obase + 1024) = y01;
    rot(y10.x, y10.y, cb, sb);  rot(y10.z, y10.w, cb, sb);
    *reinterpret_cast<float4*>(obase + 32768) = y10;
    rot(y11.x, y11.y, cb, sb);  rot(y11.z, y11.w, cb, sb);
    *reinterpret_cast<float4*>(obase + 33792) = y11;
}

extern "C" void kernel_launch(void* const* d_in, const int* in_sizes, int n_in,
                              void* d_out, int out_size)
{
    const float* rho    = (const float*)d_in[0];  // input_state [1024,1024] f32
    const float* angles = (const float*)d_in[1];  // [16] f32
    // d_in[2..4]: cos/sin/id stacks — analytically folded away, never read.
    float* out = (float*)d_out;

    // 65536 threads in a single wave: 128 blocks x 512 threads (1 CTA/SM).
    vqc_bs_density_kernel<<<128, 512>>>(rho, angles, out);
}